// round 16
// baseline (speedup 1.0000x reference)
#include <cuda_runtime.h>
#include <cstdint>

typedef unsigned long long ull;
typedef long long ll;

#define SENS   1024
#define P_CNT  256
#define KPSF   64

#define SROW   305                    // fp sBlk row stride (odd => conflict-free)
#define SK_ULL   (34 * 34)            // fp: [u 34][dy 34pad] float2(k1[u-1], k0[u])
#define SB_FLT   (32 * SROW + 4)
#define SMEM_BYTES (SK_ULL * 8 + SB_FLT * 4)

// int-role smem carve (fits inside SMEM_BYTES):
#define IB_ROW  342                   // int16 b row stride = 38*9
#define IK_HW   (2 * 33 * 34)         // k16 planes [rx][dx 33][dy 34pad]

#define ZERO_CTAS   8192
#define BINPSF_TOT  (P_CNT * 2 * 34 * 34)
#define BINPSF_CTAS ((BINPSF_TOT + 255) / 256)

// fixed-point scales (double-derived constants)
#define QS_D   (32767.0 / 0.0026)
#define QS_F   ((float)QS_D)
#define DEQ_F  ((float)(1.0 / (QS_D * 32767.0)))

// Paired binned PSF (fp): [p][ry][u 34][dy 34pad] -> float2(k_rx1[u-1], k_rx0[u])
__device__ float2 g_K[P_CNT * 2 * 34 * 34];
// Quantized binned PSF (int): [p][ry][rx][dx 33][dy 34pad] int16
__device__ short g_K16[P_CNT * 2 * 2 * 33 * 34];

__device__ __forceinline__ ull ffma2(ull a, ull b, ull c) {
    ull d;
    asm("fma.rn.f32x2 %0, %1, %2, %3;" : "=l"(d) : "l"(a), "l"(b), "l"(c));
    return d;
}
__device__ __forceinline__ ull dup2(float v) {
    ull d;
    asm("mov.b64 %0, {%1, %1};" : "=l"(d) : "f"(v));
    return d;
}
#define RED2(ptr, a, b) \
    asm volatile("red.global.add.v2.f32 [%0], {%1, %2};" :: "l"(ptr), "f"(a), "f"(b) : "memory")
#define RED1(ptr, a) \
    asm volatile("red.global.add.f32 [%0], %1;" :: "l"(ptr), "f"(a) : "memory")

// ---------------- kernel 1: setup = zero sensor + bin PSF (fp + int16) -------
__global__ void setup_kernel(const float* __restrict__ psf,
                             float4* __restrict__ out) {
    const int bid = blockIdx.x;
    if (bid < ZERO_CTAS) {
        out[bid * 256 + threadIdx.x] = make_float4(0.f, 0.f, 0.f, 0.f);
        return;
    }
    int idx = (bid - ZERO_CTAS) * 256 + threadIdx.x;
    if (idx >= BINPSF_TOT) return;
    int dy = idx % 34;
    int u  = (idx / 34) % 34;
    int ry = (idx / (34 * 34)) & 1;
    int p  = idx / (34 * 34 * 2);
    float sx = 0.f, sy = 0.f;
    if (dy < 33) {
        const float* w = psf + (size_t)p * KPSF * KPSF;
        int r0  = 63 - ry - 2 * dy;
        int cx0 = 64 - 2 * u;       // rx=1, dx=u-1
        int cy0 = 63 - 2 * u;       // rx=0, dx=u
        #pragma unroll
        for (int a = 0; a < 2; ++a) {
            int rr = r0 + a;
            if (rr < 0 || rr > 63) continue;
            const float* row = w + rr * KPSF;
            #pragma unroll
            for (int c = 0; c < 2; ++c) {
                int ccx = cx0 + c;
                if (ccx >= 0 && ccx <= 63) sx += row[ccx];
                int ccy = cy0 + c;
                if (ccy >= 0 && ccy <= 63) sy += row[ccy];
            }
        }
    }
    g_K[idx] = make_float2(sx, sy);
    // int16 planes: rx0 at dx=u (value sy), rx1 at dx=u-1 (value sx)
    if (dy < 34) {
        short* kb = g_K16 + ((size_t)p * 2 + ry) * (2 * 33 * 34);
        if (u <= 32) kb[0 * 33 * 34 + u * 34 + dy] = (short)__float2int_rn(sy * QS_F);
        if (u >= 1)  kb[1 * 33 * 34 + (u - 1) * 34 + dy] = (short)__float2int_rn(sx * QS_F);
    }
}

// ---------------- kernel 2: conv, dual-engine (fma FFMA2 / alu IMAD.WIDE) ----
// grid: 4096 CTAs = [grp 3][ry 1][p 8], heavy-first oct map. 128 thr = 4 warps.
// Role by bid%4: 25% of CTAs run the int16 engine on the ALU pipe (IMAD.WIDE,
// exact int64 accum), bypassing the f32x2 register-bank rt=3 ceiling that
// pins the fma pipe. Both engines emit via RED into the same sensor.
__global__ __launch_bounds__(128, 3)
void conv_splat_kernel(const float* __restrict__ imgs,
                       const float* __restrict__ xc,
                       const float* __restrict__ yc,
                       float* __restrict__ out)
{
    extern __shared__ ull dynsmem[];

    const int bid  = blockIdx.x;
    const int grp  = bid >> 9;
    const int oct  = (0x70615243u >> (grp * 4)) & 7;   // {3,4,2,5,1,6,0,7}
    const int ry   = bid & 1;
    const int p    = (bid >> 1) & 255;
    const int tid  = threadIdx.x;
    const int lane = tid & 31;
    const int warp = tid >> 5;
    const int bh = p & 15, bw = p >> 4;                // p = bw*16 + bh

    // splat geometry (all in-bounds for this problem's centers)
    const int ic = 512 + __float2int_rn(xc[p] * 1e6f);
    const int jc = 512 + __float2int_rn(yc[p] * 1e6f);

    if ((bid & 3) != 0) {
        // ================= FP engine (R12 body, verbatim) =================
        ull*   sK   = dynsmem;                                  // [34][34] float2
        float* sBlk = reinterpret_cast<float*>(dynsmem + SK_ULL);

        const int n    = lane & 7;
        const int xi   = (lane >> 3) & 1;
        const int sh   = lane >> 4;
        const int base = oct * 8 + warp * 2;
        const int qx   = base + xi;
        const int s0   = sh * 16;

        {
            const ulonglong2* kg = reinterpret_cast<const ulonglong2*>(
                reinterpret_cast<const ull*>(g_K) + (size_t)(p * 2 + ry) * SK_ULL);
            ulonglong2* sk2 = reinterpret_cast<ulonglong2*>(sK);
            for (int i = tid; i < SK_ULL / 2; i += 128) sk2[i] = kg[i];
        }
        for (int i = tid; i < 32 * 2 * 8; i += 128) {
            int s  = i >> 4;
            int r  = i & 15;
            int ts = (r & 1) ? 33 : 0;
            int nn = r >> 1;
            sBlk[s * SROW + ts * 9 + nn] = 0.f;
        }
        for (int i = tid; i < 32 * 8 * 8; i += 128) {
            int q  = i & 7;
            int nn = (i >> 3) & 7;
            int s  = i >> 6;
            float4 v = *reinterpret_cast<const float4*>(
                imgs + ((size_t)nn * 512 + bh * 32 + s) * 512 + bw * 32 + 4 * q);
            float* dst = &sBlk[s * SROW + (4 * q + 1) * 9 + nn];
            dst[0]  = v.x;
            dst[9]  = v.y;
            dst[18] = v.z;
            dst[27] = v.w;
        }
        __syncthreads();

        float* oemit = out + (size_t)n * SENS * SENS
                     + (size_t)(ic - 63 + ry + 2 * s0) * SENS
                     + (jc - 64 + 2 * qx);
        const int ulo = max(0, base - 31);
        const int uhi = min(33, base + 1);
        const float* bcol0 = sBlk + s0 * SROW + (qx + 1) * 9 + n;

        ull acc[40];
        #pragma unroll
        for (int i = 0; i < 40; ++i) acc[i] = 0ULL;

        #pragma unroll
        for (int i = 0; i < 16; i += 8) {
            const float* bp = bcol0 + i * SROW - ulo * 9;
            const ull*   kc = sK + ulo * 34;
            float braw[8];
            #pragma unroll
            for (int j = 0; j < 8; ++j) braw[j] = bp[j * SROW];
            for (int u = ulo; u <= uhi; ++u) {
                ull bd[8];
                #pragma unroll
                for (int j = 0; j < 8; ++j) bd[j] = dup2(braw[j]);
                bp -= 9;
                if (u < uhi) {
                    #pragma unroll
                    for (int j = 0; j < 8; ++j) braw[j] = bp[j * SROW];
                }
                ulonglong2 kk0 = *reinterpret_cast<const ulonglong2*>(kc);
                #pragma unroll
                for (int e = 0; e < 16; ++e) {
                    ulonglong2 kk1;
                    if (e < 15)
                        kk1 = *reinterpret_cast<const ulonglong2*>(kc + 2 * (e + 1));
                    #pragma unroll
                    for (int j = 0; j < 8; ++j) {
                        acc[(i + j + 2 * e)     % 40] = ffma2(kk0.x, bd[j], acc[(i + j + 2 * e)     % 40]);
                        acc[(i + j + 2 * e + 1) % 40] = ffma2(kk0.y, bd[j], acc[(i + j + 2 * e + 1) % 40]);
                    }
                    kk0 = kk1;
                }
                const ull k32 = kc[32];
                #pragma unroll
                for (int j = 0; j < 8; ++j)
                    acc[(i + j + 32) % 40] = ffma2(k32, bd[j], acc[(i + j + 32) % 40]);
                kc += 34;
            }
            #pragma unroll
            for (int j = 0; j < 8; ++j) {
                float2 v = *reinterpret_cast<float2*>(&acc[(i + j) % 40]);
                if (qx) { RED2(oemit, v.x, v.y); } else { RED1(oemit + 1, v.y); }
                acc[(i + j) % 40] = 0ULL;
                oemit += 2 * SENS;
            }
        }
        #pragma unroll
        for (int d = 16; d < 48; ++d) {
            if (ry == 1 && s0 + d == 63) { oemit += 2 * SENS; continue; }
            float2 v = *reinterpret_cast<float2*>(&acc[d % 40]);
            if (qx) { RED2(oemit, v.x, v.y); } else { RED1(oemit + 1, v.y); }
            oemit += 2 * SENS;
        }
    } else {
        // ================= INT engine (ALU pipe, IMAD.WIDE) =================
        short* sKi = reinterpret_cast<short*>(dynsmem);           // [2][33][34]
        short* sB16 = sKi + IK_HW;                                // [32][38*9]

        const int n    = lane & 7;
        const int q4   = lane >> 3;           // 0..3
        const int quad = warp & 1;
        const int rxw  = warp >> 1;
        const int qbase = oct * 8 + quad * 4;
        const int qx    = qbase + q4;

        // load quantized kernel planes (as u32 copies)
        {
            const uint32_t* kg = reinterpret_cast<const uint32_t*>(
                g_K16 + ((size_t)p * 2 + ry) * IK_HW);
            uint32_t* sk = reinterpret_cast<uint32_t*>(sKi);
            for (int i = tid; i < IK_HW / 2; i += 128) sk[i] = kg[i];
        }
        // zero pad t-columns: ts in {0,1,2,35,36,37} (t = ts-3)
        for (int i = tid; i < 32 * 6 * 9; i += 128) {
            int s = i / 54;
            int r = i % 54;
            int tsi = r / 9;                 // 0..5
            int nn  = r % 9;
            int ts  = (tsi < 3) ? tsi : (tsi + 32);
            sB16[s * IB_ROW + ts * 9 + nn] = 0;
        }
        // fill interior: b16 = rn(b * 32767)
        for (int i = tid; i < 32 * 32 * 8; i += 128) {
            int t  = i & 31;
            int nn = (i >> 5) & 7;
            int s  = i >> 8;
            float b = imgs[((size_t)nn * 512 + bh * 32 + s) * 512 + bw * 32 + t];
            sB16[s * IB_ROW + (t + 3) * 9 + nn] = (short)__float2int_rn(b * 32767.0f);
        }
        __syncthreads();

        const int dlo = max(0, qbase - 31);
        const int dhi = min(32, qbase + 3);
        const short* kw = sKi + rxw * (33 * 34);
        const bool emit_ok = !(rxw == 1 && qx == 63);

        float* oemit = out + (size_t)n * SENS * SENS
                     + (size_t)(ic - 63 + ry) * SENS
                     + (jc - 63 + 2 * qx + rxw);

        ll acc[40];
        #pragma unroll
        for (int i = 0; i < 40; ++i) acc[i] = 0;

        #pragma unroll
        for (int i = 0; i < 32; i += 8) {
            const short* bp = sB16 + i * IB_ROW + (qx - dlo + 3) * 9 + n;
            for (int dx = dlo; dx <= dhi; ++dx) {
                int bv[8];
                #pragma unroll
                for (int j = 0; j < 8; ++j) bv[j] = bp[j * IB_ROW];
                bp -= 9;
                const short* kc = kw + dx * 34;
                int k0 = kc[0];
                #pragma unroll
                for (int d = 0; d < 33; ++d) {
                    int kn = 0;
                    if (d < 32) kn = kc[d + 1];
                    #pragma unroll
                    for (int j = 0; j < 8; ++j)
                        acc[(i + j + d) % 40] += (ll)k0 * bv[j];
                    k0 = kn;
                }
            }
            // qy = i..i+7 complete: dequant, emit, recycle
            #pragma unroll
            for (int j = 0; j < 8; ++j) {
                float v = (float)acc[(i + j) % 40] * DEQ_F;
                if (emit_ok) RED1(oemit, v);
                acc[(i + j) % 40] = 0;
                oemit += 2 * SENS;
            }
        }
        // drain qy = 32..63
        #pragma unroll
        for (int qy = 32; qy < 64; ++qy) {
            if (ry == 1 && qy == 63) continue;
            float v = (float)acc[qy % 40] * DEQ_F;
            if (emit_ok) RED1(oemit, v);
            oemit += 2 * SENS;
        }
    }
}

// ---------------- launch ----------------
extern "C" void kernel_launch(void* const* d_in, const int* in_sizes, int n_in,
                              void* d_out, int out_size) {
    const float* imgs = (const float*)d_in[0];
    const float* psf  = (const float*)d_in[1];
    const float* xc   = (const float*)d_in[4];
    const float* yc   = (const float*)d_in[5];
    float* out = (float*)d_out;

    (void)cudaFuncSetAttribute(conv_splat_kernel,
                               cudaFuncAttributeMaxDynamicSharedMemorySize, SMEM_BYTES);

    setup_kernel<<<ZERO_CTAS + BINPSF_CTAS, 256>>>(psf, (float4*)out);
    conv_splat_kernel<<<P_CNT * 2 * 8, 128, SMEM_BYTES>>>(imgs, xc, yc, out);
}

// round 17
// speedup vs baseline: 1.6055x; 1.6055x over previous
#include <cuda_runtime.h>
#include <cstdint>

typedef unsigned long long ull;

#define SENS   1024
#define P_CNT  256
#define KPSF   64

#define SROW   305                    // sBlk row stride (odd => conflict-free)
#define KCOL   36                     // kernel column stride (ull): [dy0..16 | pad | dy17..32 | pad,pad]
#define SK_ULL   (34 * KCOL)          // [u 34][KCOL] float2(k_rx1[u-1], k_rx0[u])
#define SB_FLT   (32 * SROW + 4)
#define SMEM_BYTES (SK_ULL * 8 + SB_FLT * 4)

#define ZERO_CTAS   8192
#define BINPSF_TOT  (P_CNT * 2 * 34 * KCOL)
#define BINPSF_CTAS ((BINPSF_TOT + 255) / 256)

// Paired binned PSF: [p][ry][u 34][KCOL] -> float2(k_rx1[u-1], k_rx0[u])
// column slots: 0..16 = dy 0..16, 17 = 0, 18..33 = dy 17..32, 34..35 = 0
__device__ float2 g_K[P_CNT * 2 * 34 * KCOL];

__device__ __forceinline__ ull ffma2(ull a, ull b, ull c) {
    ull d;
    asm("fma.rn.f32x2 %0, %1, %2, %3;" : "=l"(d) : "l"(a), "l"(b), "l"(c));
    return d;
}
__device__ __forceinline__ ull dup2(float v) {
    ull d;
    asm("mov.b64 %0, {%1, %1};" : "=l"(d) : "f"(v));
    return d;
}
#define RED2(ptr, a, b) \
    asm volatile("red.global.add.v2.f32 [%0], {%1, %2};" :: "l"(ptr), "f"(a), "f"(b) : "memory")
#define RED1(ptr, a) \
    asm volatile("red.global.add.f32 [%0], %1;" :: "l"(ptr), "f"(a) : "memory")

// ---------------- kernel 1: setup = zero sensor + bin PSF (merged) -----------
__global__ void setup_kernel(const float* __restrict__ psf,
                             float4* __restrict__ out) {
    const int bid = blockIdx.x;
    if (bid < ZERO_CTAS) {
        out[bid * 256 + threadIdx.x] = make_float4(0.f, 0.f, 0.f, 0.f);
        return;
    }
    int idx = (bid - ZERO_CTAS) * 256 + threadIdx.x;
    if (idx >= BINPSF_TOT) return;
    int slot = idx % KCOL;
    int u  = (idx / KCOL) % 34;
    int ry = (idx / (KCOL * 34)) & 1;
    int p  = idx / (KCOL * 34 * 2);
    // map slot -> dy (or -1 for pad)
    int dy = -1;
    if (slot < 17) dy = slot;
    else if (slot >= 18 && slot < 34) dy = slot - 1;
    float sx = 0.f, sy = 0.f;
    if (dy >= 0 && dy < 33) {
        const float* w = psf + (size_t)p * KPSF * KPSF;
        int r0  = 63 - ry - 2 * dy;
        int cx0 = 64 - 2 * u;       // rx=1, dx=u-1
        int cy0 = 63 - 2 * u;       // rx=0, dx=u
        #pragma unroll
        for (int a = 0; a < 2; ++a) {
            int rr = r0 + a;
            if (rr < 0 || rr > 63) continue;
            const float* row = w + rr * KPSF;
            #pragma unroll
            for (int c = 0; c < 2; ++c) {
                int ccx = cx0 + c;
                if (ccx >= 0 && ccx <= 63) sx += row[ccx];
                int ccy = cy0 + c;
                if (ccy >= 0 && ccy <= 63) sy += row[ccy];
            }
        }
    }
    g_K[idx] = make_float2(sx, sy);
}

// ---------------- kernel 2: conv, dy-split lanes, ring 25, occ 4 -------------
// grid: 4096 CTAs (heavy-first oct). 128 threads = 4 warps; warp w: qx base =
// oct*8 + 2w. lane: n = lane&7, xi = (lane>>3)&1, dyh = lane>>4 (dy half).
// Each thread sweeps all 32 rows accumulating 17 dy-taps (dyh1's 17th is a
// zero pad) -> 25-slot rotating ring (50 regs) -> fits occ 4 without spills.
__global__ __launch_bounds__(128, 4)
void conv_splat_kernel(const float* __restrict__ imgs,
                       const float* __restrict__ xc,
                       const float* __restrict__ yc,
                       float* __restrict__ out)
{
    extern __shared__ ull dynsmem[];
    ull*   sK   = dynsmem;                                  // [34][KCOL] float2
    float* sBlk = reinterpret_cast<float*>(dynsmem + SK_ULL);

    const int bid  = blockIdx.x;
    // heavy-first octet ordering: groups of 512 CTAs, descending u-trip work
    const int grp  = bid >> 9;
    const int oct  = (0x70615243u >> (grp * 4)) & 7;   // {3,4,2,5,1,6,0,7}
    const int ry   = bid & 1;
    const int p    = (bid >> 1) & 255;
    const int tid  = threadIdx.x;
    const int lane = tid & 31;
    const int warp = tid >> 5;
    const int n    = lane & 7;
    const int xi   = (lane >> 3) & 1;
    const int dyh  = lane >> 4;
    const int base = oct * 8 + warp * 2;
    const int qx   = base + xi;

    // load paired kernel (16B vectors)
    {
        const ulonglong2* kg = reinterpret_cast<const ulonglong2*>(
            reinterpret_cast<const ull*>(g_K) + (size_t)(p * 2 + ry) * SK_ULL);
        ulonglong2* sk2 = reinterpret_cast<ulonglong2*>(sK);
        for (int i = tid; i < SK_ULL / 2; i += 128) sk2[i] = kg[i];
    }
    // zero the two pad t-columns (ts = 0 and ts = 33)
    for (int i = tid; i < 32 * 2 * 8; i += 128) {
        int s  = i >> 4;
        int r  = i & 15;
        int ts = (r & 1) ? 33 : 0;
        int nn = r >> 1;
        sBlk[s * SROW + ts * 9 + nn] = 0.f;
    }
    // fill interior with float4 gmem loads (stride-9 scalar STS, conflict-free)
    const int bh = p & 15, bw = p >> 4;          // p = bw*16 + bh
    for (int i = tid; i < 32 * 8 * 8; i += 128) {
        int q  = i & 7;
        int nn = (i >> 3) & 7;
        int s  = i >> 6;
        float4 v = *reinterpret_cast<const float4*>(
            imgs + ((size_t)nn * 512 + bh * 32 + s) * 512 + bw * 32 + 4 * q);
        float* dst = &sBlk[s * SROW + (4 * q + 1) * 9 + nn];
        dst[0]      = v.x;
        dst[9]      = v.y;
        dst[18]     = v.z;
        dst[27]     = v.w;
    }
    __syncthreads();

    // splat geometry (all in-bounds). This lane emits qy = qy_local + 17*dyh.
    const int ic = 512 + __float2int_rn(xc[p] * 1e6f);
    const int jc = 512 + __float2int_rn(yc[p] * 1e6f);
    float* oemit = out + (size_t)n * SENS * SENS
                 + (size_t)(ic - 63 + ry + 34 * dyh) * SENS
                 + (jc - 64 + 2 * qx);

    // warp-uniform u range (union of useful taps over 2 qx)
    const int ulo = max(0, base - 31);
    const int uhi = min(33, base + 1);

    const ull*   kpl   = sK + dyh * 18;               // this lane's dy half
    const float* bcol0 = sBlk + (qx + 1) * 9 + n;     // (s = 0, ts = qx+1)

    ull acc[25];
    #pragma unroll
    for (int i = 0; i < 25; ++i) acc[i] = 0ULL;

    #pragma unroll
    for (int i = 0; i < 32; i += 8) {               // 4 groups of 8 s-steps
        const float* bp = bcol0 + i * SROW - ulo * 9;
        const ull*   kc = kpl + ulo * KCOL;
        float braw[8];
        #pragma unroll
        for (int j = 0; j < 8; ++j) braw[j] = bp[j * SROW];
        for (int u = ulo; u <= uhi; ++u) {
            ull bd[8];
            #pragma unroll
            for (int j = 0; j < 8; ++j) bd[j] = dup2(braw[j]);
            bp -= 9;
            if (u < uhi) {
                #pragma unroll
                for (int j = 0; j < 8; ++j) braw[j] = bp[j * SROW];
            }
            // 8 pairs (dy' 0..15) double-buffered + scalar tail (dy' 16)
            ulonglong2 kk0 = *reinterpret_cast<const ulonglong2*>(kc);
            #pragma unroll
            for (int e = 0; e < 8; ++e) {
                ulonglong2 kk1;
                if (e < 7)
                    kk1 = *reinterpret_cast<const ulonglong2*>(kc + 2 * (e + 1));
                #pragma unroll
                for (int j = 0; j < 8; ++j) {
                    acc[(i + j + 2 * e)     % 25] = ffma2(kk0.x, bd[j], acc[(i + j + 2 * e)     % 25]);
                    acc[(i + j + 2 * e + 1) % 25] = ffma2(kk0.y, bd[j], acc[(i + j + 2 * e + 1) % 25]);
                }
                kk0 = kk1;
            }
            const ull k16 = kc[16];
            #pragma unroll
            for (int j = 0; j < 8; ++j)
                acc[(i + j + 16) % 25] = ffma2(k16, bd[j], acc[(i + j + 16) % 25]);
            kc += KCOL;
        }
        // qy_local = i .. i+7 complete for this dy half: emit, recycle slots
        #pragma unroll
        for (int j = 0; j < 8; ++j) {
            float2 v = *reinterpret_cast<float2*>(&acc[(i + j) % 25]);
            if (qx) { RED2(oemit, v.x, v.y); } else { RED1(oemit + 1, v.y); }
            acc[(i + j) % 25] = 0ULL;
            oemit += 2 * SENS;
        }
    }

    // drain qy_local = 32..47 (real qy = qy_local + 17*dyh)
    #pragma unroll
    for (int d = 32; d < 48; ++d) {
        const int qy = d + 17 * dyh;
        if (qy <= 63 && !(ry == 1 && qy == 63)) {
            float2 v = *reinterpret_cast<float2*>(&acc[d % 25]);
            if (qx) { RED2(oemit, v.x, v.y); } else { RED1(oemit + 1, v.y); }
        }
        oemit += 2 * SENS;
    }
}

// ---------------- launch ----------------
extern "C" void kernel_launch(void* const* d_in, const int* in_sizes, int n_in,
                              void* d_out, int out_size) {
    const float* imgs = (const float*)d_in[0];
    const float* psf  = (const float*)d_in[1];
    const float* xc   = (const float*)d_in[4];
    const float* yc   = (const float*)d_in[5];
    float* out = (float*)d_out;

    (void)cudaFuncSetAttribute(conv_splat_kernel,
                               cudaFuncAttributeMaxDynamicSharedMemorySize, SMEM_BYTES);

    setup_kernel<<<ZERO_CTAS + BINPSF_CTAS, 256>>>(psf, (float4*)out);
    conv_splat_kernel<<<P_CNT * 2 * 8, 128, SMEM_BYTES>>>(imgs, xc, yc, out);
}